// round 8
// baseline (speedup 1.0000x reference)
#include <cuda_runtime.h>
#include <cuda_bf16.h>
#include <math.h>
#include <cstdint>

#define BATCH 131072
#define CD 16
#define HID 256

// ---------------- smem map (bytes) ----------------
#define SW2      0          // 98304 : W2q kt0..5
#define SW1      98304      // 32768 : W1q, later W2q kt6,7
#define SW3      131072     // 8192  : W3q
#define A2H      139264     // 34816 : activation hi plane, 128 rows x 272B
#define A2L      174080     // 34816 : lo plane
#define SC_ISB1  208896
#define SC_ISB2  209920
#define SC_B1    210944
#define SC_B2    211968
#define SC_ISB3  212992
#define SC_B3    213056
#define SM_TOTAL 213120

// ---------------- scratch globals ----------------
__device__ __align__(16) float g_W3B[HID * CD];
__device__ __align__(16) float g_b3B[CD];
__device__ __align__(16) float g_bias1[HID];
__device__ __align__(16) float g_invSw1[HID];
__device__ __align__(16) float g_invSw2[HID];
__device__ __align__(16) float g_invSw3[CD];
__device__ __align__(16) uint4 g_W1q[2 * 32 * 32];   // [kt][n2][lane]
__device__ __align__(16) uint4 g_W2q[8 * 32 * 32];
__device__ __align__(16) uint4 g_W3q[8 * 2 * 32];
__device__ float g_pB[BATCH * CD];
__device__ int   g_K;

// ---------------- helpers ----------------
__device__ __forceinline__ uint32_t smem_u32(const void* p) {
    uint32_t a;
    asm("{ .reg .u64 t; cvta.to.shared.u64 t, %1; cvt.u32.u64 %0, t; }" : "=r"(a) : "l"(p));
    return a;
}
#define CPA16(dst, src) asm volatile("cp.async.cg.shared.global [%0], [%1], 16;" :: "r"((uint32_t)(dst)), "l"(src))
#define CPA_COMMIT()    asm volatile("cp.async.commit_group;" ::: "memory")
#define CPA_WAIT(n)     asm volatile("cp.async.wait_group %0;" :: "n"(n) : "memory")

#define IMMA(D, A, b0, b1) \
    asm volatile("mma.sync.aligned.m16n8k32.row.col.s32.s8.s8.s32 " \
        "{%0,%1,%2,%3}, {%4,%5,%6,%7}, {%8,%9}, {%0,%1,%2,%3};" \
        : "+r"((D)[0]), "+r"((D)[1]), "+r"((D)[2]), "+r"((D)[3]) \
        : "r"((A)[0]), "r"((A)[1]), "r"((A)[2]), "r"((A)[3]), "r"(b0), "r"(b1))

__device__ __forceinline__ uint32_t pack4(int a, int b, int c, int d) {
    return (uint32_t)(a & 255) | ((uint32_t)(b & 255) << 8) |
           ((uint32_t)(c & 255) << 16) | ((uint32_t)(d & 255) << 24);
}
// q[0..3] = k+0..3, q[4..7] = k+16..19 -> fragment uint4 {hi_lo16, hi_hi16, lo_lo16, lo_hi16}
__device__ __forceinline__ uint4 packq8(const int* q) {
    int ah[8], al[8];
#pragma unroll
    for (int i = 0; i < 8; i++) { ah[i] = (q[i] + 64) >> 7; al[i] = q[i] - (ah[i] << 7); }
    uint4 r;
    r.x = pack4(ah[0], ah[1], ah[2], ah[3]);
    r.y = pack4(ah[4], ah[5], ah[6], ah[7]);
    r.z = pack4(al[0], al[1], al[2], al[3]);
    r.w = pack4(al[4], al[5], al[6], al[7]);
    return r;
}
// quantize float4 with scale S into hi/lo s8x4 packed
__device__ __forceinline__ void quant4(float4 v, float S, uint32_t& hi, uint32_t& lo) {
    int q0 = __float2int_rn(v.x * S), q1 = __float2int_rn(v.y * S);
    int q2 = __float2int_rn(v.z * S), q3 = __float2int_rn(v.w * S);
    int h0 = (q0 + 64) >> 7, h1 = (q1 + 64) >> 7, h2 = (q2 + 64) >> 7, h3 = (q3 + 64) >> 7;
    hi = pack4(h0, h1, h2, h3);
    lo = pack4(q0 - (h0 << 7), q1 - (h1 << 7), q2 - (h2 << 7), q3 - (h3 << 7));
}

// ---------------- k_prep: W3B = W3 @ Bmat, b3B, reset K ----------------
__global__ void k_prep(const float* __restrict__ W3, const float* __restrict__ b3,
                       const float* __restrict__ Bm) {
    int h = threadIdx.x;
    float acc[CD];
#pragma unroll
    for (int j = 0; j < CD; j++) acc[j] = 0.0f;
    for (int d = 0; d < 64; d++) {
        float w = W3[h * 64 + d];
#pragma unroll
        for (int j = 0; j < CD; j++) acc[j] += w * Bm[d * CD + j];
    }
#pragma unroll
    for (int j = 0; j < CD; j++) g_W3B[h * CD + j] = acc[j];
    if (h < CD) {
        float a = 0.0f;
        for (int d = 0; d < 64; d++) a += b3[d] * Bm[d * CD + h];
        g_b3B[h] = a;
    }
    if (h == 0) g_K = 0;
}

// ---------------- k_quant: weights -> fragment-ordered s8 hi/lo ----------------
__global__ void k_quant(const float* __restrict__ W1, const float* __restrict__ b1,
                        const float* __restrict__ W2, const float* __restrict__ t) {
    int tid = threadIdx.x;
    int blk = blockIdx.x;
    if (blk == 0) {
        // ---- W1 (thread = column n) ----
        int n = tid;
        float mx = 1e-30f;
        for (int k = 0; k < 64; k++) mx = fmaxf(mx, fabsf(W1[k * HID + n]));
        float S = 16000.f / mx;
        g_invSw1[n] = mx * (1.f / 16000.f);
#pragma unroll
        for (int kt = 0; kt < 2; kt++)
#pragma unroll
            for (int kq = 0; kq < 4; kq++) {
                int kb = kt * 32 + kq * 4;
                int q[8];
#pragma unroll
                for (int i = 0; i < 4; i++) {
                    q[i]     = __float2int_rn(W1[(kb + i) * HID + n] * S);
                    q[4 + i] = __float2int_rn(W1[(kb + 16 + i) * HID + n] * S);
                }
                g_W1q[(kt * 32 + (n >> 3)) * 32 + (n & 7) * 4 + kq] = packq8(q);
            }
        g_bias1[n] = fmaf(t[0], W1[64 * HID + n], b1[n]);
        // ---- W3B (threads 0..15) ----
        if (n < CD) {
            float mx3 = 1e-30f;
            for (int k = 0; k < HID; k++) mx3 = fmaxf(mx3, fabsf(g_W3B[k * CD + n]));
            float S3 = 16000.f / mx3;
            g_invSw3[n] = mx3 * (1.f / 16000.f);
#pragma unroll
            for (int kt = 0; kt < 8; kt++)
#pragma unroll
                for (int kq = 0; kq < 4; kq++) {
                    int kb = kt * 32 + kq * 4;
                    int q[8];
#pragma unroll
                    for (int i = 0; i < 4; i++) {
                        q[i]     = __float2int_rn(g_W3B[(kb + i) * CD + n] * S3);
                        q[4 + i] = __float2int_rn(g_W3B[(kb + 16 + i) * CD + n] * S3);
                    }
                    g_W3q[(kt * 2 + (n >> 3)) * 32 + (n & 7) * 4 + kq] = packq8(q);
                }
        }
    } else {
        // ---- W2: block handles 8 columns; warp = one column ----
        int c = tid >> 5, l = tid & 31;
        int n = (blk - 1) * 8 + c;
        int kt = l >> 2, kq = l & 3;
        int kb = kt * 32 + kq * 4;
        float v[8];
#pragma unroll
        for (int i = 0; i < 4; i++) {
            v[i]     = W2[(kb + i) * HID + n];
            v[4 + i] = W2[(kb + 16 + i) * HID + n];
        }
        float mx = 1e-30f;
#pragma unroll
        for (int i = 0; i < 8; i++) mx = fmaxf(mx, fabsf(v[i]));
#pragma unroll
        for (int o = 16; o > 0; o >>= 1)
            mx = fmaxf(mx, __shfl_xor_sync(0xffffffffu, mx, o));
        float S = 16000.f / mx;
        if (l == 0) g_invSw2[n] = mx * (1.f / 16000.f);
        int q[8];
#pragma unroll
        for (int i = 0; i < 8; i++) q[i] = __float2int_rn(v[i] * S);
        g_W2q[(kt * 32 + (n >> 3)) * 32 + (n & 7) * 4 + kq] = packq8(q);
    }
}

// per-row dynamic scale from vh (quad-cooperative: quad lanes share rows)
__device__ __forceinline__ void rowscales(const float (&vh)[32][4], float& Sa0, float& Sa8,
                                          float& invSa0, float& invSa8) {
    float m0 = 1e-30f, m8 = 1e-30f;
#pragma unroll
    for (int tn = 0; tn < 32; tn++) {
        m0 = fmaxf(m0, fmaxf(fabsf(vh[tn][0]), fabsf(vh[tn][1])));
        m8 = fmaxf(m8, fmaxf(fabsf(vh[tn][2]), fabsf(vh[tn][3])));
    }
    m0 = fmaxf(m0, __shfl_xor_sync(0xffffffffu, m0, 1));
    m0 = fmaxf(m0, __shfl_xor_sync(0xffffffffu, m0, 2));
    m8 = fmaxf(m8, __shfl_xor_sync(0xffffffffu, m8, 1));
    m8 = fmaxf(m8, __shfl_xor_sync(0xffffffffu, m8, 2));
    Sa0 = 16000.f / m0; Sa8 = 16000.f / m8;
    invSa0 = m0 * (1.f / 16000.f); invSa8 = m8 * (1.f / 16000.f);
}

// quantize vh rows into A planes (warp-private rows)
__device__ __forceinline__ void quant_store(char* sm, const float (&vh)[32][4],
                                            float Sa0, float Sa8, int rA, int q) {
#pragma unroll
    for (int tn = 0; tn < 32; tn++) {
        int c0 = tn * 8 + 2 * q;
        int q0 = __float2int_rn(vh[tn][0] * Sa0), q1 = __float2int_rn(vh[tn][1] * Sa0);
        int h0 = (q0 + 64) >> 7, h1 = (q1 + 64) >> 7;
        *(uint16_t*)(sm + A2H + rA * 272 + c0) = (uint16_t)((h0 & 255) | ((h1 & 255) << 8));
        *(uint16_t*)(sm + A2L + rA * 272 + c0) =
            (uint16_t)(((q0 - (h0 << 7)) & 255) | (((q1 - (h1 << 7)) & 255) << 8));
        int q2 = __float2int_rn(vh[tn][2] * Sa8), q3 = __float2int_rn(vh[tn][3] * Sa8);
        int h2 = (q2 + 64) >> 7, h3 = (q3 + 64) >> 7;
        *(uint16_t*)(sm + A2H + (rA + 8) * 272 + c0) = (uint16_t)((h2 & 255) | ((h3 & 255) << 8));
        *(uint16_t*)(sm + A2L + (rA + 8) * 272 + c0) =
            (uint16_t)(((q2 - (h2 << 7)) & 255) | (((q3 - (h3 << 7)) & 255) << 8));
    }
}

// load s8 A fragments for one k32 step
__device__ __forceinline__ void loadA(const char* sm, int rA, int kt, int q,
                                      uint32_t (&Ah)[4], uint32_t (&Al)[4]) {
    const char* p = sm + A2H + rA * 272 + kt * 32 + 4 * q;
    Ah[0] = *(const uint32_t*)p;
    Ah[1] = *(const uint32_t*)(p + 8 * 272);
    Ah[2] = *(const uint32_t*)(p + 16);
    Ah[3] = *(const uint32_t*)(p + 8 * 272 + 16);
    const char* pl = p + (A2L - A2H);
    Al[0] = *(const uint32_t*)pl;
    Al[1] = *(const uint32_t*)(pl + 8 * 272);
    Al[2] = *(const uint32_t*)(pl + 16);
    Al[3] = *(const uint32_t*)(pl + 8 * 272 + 16);
}

// ---------------- fused int8 MLP ----------------
__global__ void __launch_bounds__(256, 1) k_mlp(const float* __restrict__ x,
                                                const float* __restrict__ b2) {
    extern __shared__ char sm[];
    uint32_t smb = smem_u32(sm);
    int tid = threadIdx.x, wid = tid >> 5, lid = tid & 31;
    int q = lid & 3, r0 = lid >> 2;
    int rA = wid * 16 + r0;
    int row0 = blockIdx.x * 128;
    int R0g = row0 + rA, R8g = R0g + 8;

    // C0: W1q, W3q, scales/biases
    for (int i = tid; i < 2048; i += 256) CPA16(smb + SW1 + i * 16, g_W1q + i);
    for (int i = tid; i < 512;  i += 256) CPA16(smb + SW3 + i * 16, g_W3q + i);
    if (tid < 64) {
        CPA16(smb + SC_ISB1 + tid * 16, (const char*)g_invSw1 + tid * 16);
        CPA16(smb + SC_ISB2 + tid * 16, (const char*)g_invSw2 + tid * 16);
        CPA16(smb + SC_B1 + tid * 16, (const char*)g_bias1 + tid * 16);
        CPA16(smb + SC_B2 + tid * 16, (const char*)b2 + tid * 16);
    } else if (tid < 68) {
        CPA16(smb + SC_ISB3 + (tid - 64) * 16, (const char*)g_invSw3 + (tid - 64) * 16);
    } else if (tid < 72) {
        CPA16(smb + SC_B3 + (tid - 68) * 16, (const char*)g_b3B + (tid - 68) * 16);
    }
    CPA_COMMIT();                                   // C0
    for (int i = tid; i < 6144; i += 256) CPA16(smb + SW2 + i * 16, g_W2q + i);
    CPA_COMMIT();                                   // C1: W2 kt0..5

    // ---- x rows -> per-row scale + layer-1 A fragments ----
    float4 xv0[4], xv8[4];
#pragma unroll
    for (int g = 0; g < 4; g++) {
        xv0[g] = *(const float4*)(x + R0g * 64 + g * 16 + 4 * q);
        xv8[g] = *(const float4*)(x + R8g * 64 + g * 16 + 4 * q);
    }
    float m0 = 1e-30f, m8 = 1e-30f;
#pragma unroll
    for (int g = 0; g < 4; g++) {
        m0 = fmaxf(m0, fmaxf(fmaxf(fabsf(xv0[g].x), fabsf(xv0[g].y)),
                             fmaxf(fabsf(xv0[g].z), fabsf(xv0[g].w))));
        m8 = fmaxf(m8, fmaxf(fmaxf(fabsf(xv8[g].x), fabsf(xv8[g].y)),
                             fmaxf(fabsf(xv8[g].z), fabsf(xv8[g].w))));
    }
    m0 = fmaxf(m0, __shfl_xor_sync(0xffffffffu, m0, 1));
    m0 = fmaxf(m0, __shfl_xor_sync(0xffffffffu, m0, 2));
    m8 = fmaxf(m8, __shfl_xor_sync(0xffffffffu, m8, 1));
    m8 = fmaxf(m8, __shfl_xor_sync(0xffffffffu, m8, 2));
    float Sa0 = 16000.f / m0, Sa8 = 16000.f / m8;
    float invSa0 = m0 * (1.f / 16000.f), invSa8 = m8 * (1.f / 16000.f);

    uint32_t A1h[2][4], A1l[2][4];
#pragma unroll
    for (int kt = 0; kt < 2; kt++) {
        quant4(xv0[2 * kt],     Sa0, A1h[kt][0], A1l[kt][0]);
        quant4(xv8[2 * kt],     Sa8, A1h[kt][1], A1l[kt][1]);
        quant4(xv0[2 * kt + 1], Sa0, A1h[kt][2], A1l[kt][2]);
        quant4(xv8[2 * kt + 1], Sa8, A1h[kt][3], A1l[kt][3]);
    }

    CPA_WAIT(1);        // C0 landed
    __syncthreads();

    float vh[32][4];

    // ---- Layer 1: K=64 (2 k32), 8 strips of 4 n8-tiles ----
#pragma unroll
    for (int s = 0; s < 8; s++) {
        int a1[4][4] = {}, a2[4][4] = {};
#pragma unroll
        for (int kt = 0; kt < 2; kt++)
#pragma unroll
            for (int j = 0; j < 4; j++) {
                int n2 = s * 4 + j;
                uint4 B = *(const uint4*)(sm + SW1 + (((kt * 32 + n2) * 32 + lid) << 4));
                IMMA(a1[j], A1h[kt], B.x, B.y);
                IMMA(a2[j], A1h[kt], B.z, B.w);
                IMMA(a2[j], A1l[kt], B.x, B.y);
            }
#pragma unroll
        for (int j = 0; j < 4; j++) {
            int tn = s * 4 + j;
            int c0 = tn * 8 + 2 * q;
            float2 isb = *(const float2*)(sm + SC_ISB1 + c0 * 4);
            float2 bs  = *(const float2*)(sm + SC_B1 + c0 * 4);
            vh[tn][0] = fmaxf(fmaf(16384.f * (float)a1[j][0] + 128.f * (float)a2[j][0], invSa0 * isb.x, bs.x), 0.f);
            vh[tn][1] = fmaxf(fmaf(16384.f * (float)a1[j][1] + 128.f * (float)a2[j][1], invSa0 * isb.y, bs.y), 0.f);
            vh[tn][2] = fmaxf(fmaf(16384.f * (float)a1[j][2] + 128.f * (float)a2[j][2], invSa8 * isb.x, bs.x), 0.f);
            vh[tn][3] = fmaxf(fmaf(16384.f * (float)a1[j][3] + 128.f * (float)a2[j][3], invSa8 * isb.y, bs.y), 0.f);
        }
    }
    __syncthreads();    // all reads of SW1 done
    for (int i = tid; i < 2048; i += 256) CPA16(smb + SW1 + i * 16, g_W2q + 6144 + i);
    CPA_COMMIT();       // C2: W2 kt6,7 -> SW1

    rowscales(vh, Sa0, Sa8, invSa0, invSa8);
    quant_store(sm, vh, Sa0, Sa8, rA, q);
    __syncwarp();
    CPA_WAIT(0);
    __syncthreads();

    // ---- Layer 2: K=256 (8 k32) ----
#pragma unroll
    for (int s = 0; s < 8; s++) {
        int a1[4][4] = {}, a2[4][4] = {};
#pragma unroll
        for (int kt = 0; kt < 8; kt++) {
            uint32_t Ah[4], Al[4];
            loadA(sm, rA, kt, q, Ah, Al);
            const char* wb = (kt < 6) ? (sm + SW2 + kt * 16384)
                                      : (sm + SW1 + (kt - 6) * 16384);
#pragma unroll
            for (int j = 0; j < 4; j++) {
                int n2 = s * 4 + j;
                uint4 B = *(const uint4*)(wb + ((n2 * 32 + lid) << 4));
                IMMA(a1[j], Ah, B.x, B.y);
                IMMA(a2[j], Ah, B.z, B.w);
                IMMA(a2[j], Al, B.x, B.y);
            }
        }
#pragma unroll
        for (int j = 0; j < 4; j++) {
            int tn = s * 4 + j;
            int c0 = tn * 8 + 2 * q;
            float2 isb = *(const float2*)(sm + SC_ISB2 + c0 * 4);
            float2 bs  = *(const float2*)(sm + SC_B2 + c0 * 4);
            vh[tn][0] = fmaxf(fmaf(16384.f * (float)a1[j][0] + 128.f * (float)a2[j][0], invSa0 * isb.x, bs.x), 0.f);
            vh[tn][1] = fmaxf(fmaf(16384.f * (float)a1[j][1] + 128.f * (float)a2[j][1], invSa0 * isb.y, bs.y), 0.f);
            vh[tn][2] = fmaxf(fmaf(16384.f * (float)a1[j][2] + 128.f * (float)a2[j][2], invSa8 * isb.x, bs.x), 0.f);
            vh[tn][3] = fmaxf(fmaf(16384.f * (float)a1[j][3] + 128.f * (float)a2[j][3], invSa8 * isb.y, bs.y), 0.f);
        }
    }
    __syncwarp();       // this warp's A2 reads done (rows warp-private)

    rowscales(vh, Sa0, Sa8, invSa0, invSa8);
    quant_store(sm, vh, Sa0, Sa8, rA, q);
    __syncwarp();

    // ---- Layer 3: N=16 (2 n8-tiles), K=256 ----
    int a1[2][4] = {}, a2[2][4] = {};
#pragma unroll
    for (int kt = 0; kt < 8; kt++) {
        uint32_t Ah[4], Al[4];
        loadA(sm, rA, kt, q, Ah, Al);
#pragma unroll
        for (int j = 0; j < 2; j++) {
            uint4 B = *(const uint4*)(sm + SW3 + (((kt * 2 + j) * 32 + lid) << 4));
            IMMA(a1[j], Ah, B.x, B.y);
            IMMA(a2[j], Ah, B.z, B.w);
            IMMA(a2[j], Al, B.x, B.y);
        }
    }

    // ---- epilogue: pB = acc*scale + b3B ----
    {
        const float* isb3 = (const float*)(sm + SC_ISB3);
        const float* b3s  = (const float*)(sm + SC_B3);
#pragma unroll
        for (int j = 0; j < 2; j++) {
            int c0 = j * 8 + 2 * q;
            float2 v;
            v.x = fmaf(16384.f * (float)a1[j][0] + 128.f * (float)a2[j][0], invSa0 * isb3[c0],     b3s[c0]);
            v.y = fmaf(16384.f * (float)a1[j][1] + 128.f * (float)a2[j][1], invSa0 * isb3[c0 + 1], b3s[c0 + 1]);
            *(float2*)(g_pB + R0g * 16 + c0) = v;
            v.x = fmaf(16384.f * (float)a1[j][2] + 128.f * (float)a2[j][2], invSa8 * isb3[c0],     b3s[c0]);
            v.y = fmaf(16384.f * (float)a1[j][3] + 128.f * (float)a2[j][3], invSa8 * isb3[c0 + 1], b3s[c0 + 1]);
            *(float2*)(g_pB + R8g * 16 + c0) = v;
        }
    }
}

// ---------------- k_count: exact while-loop replication ----------------
__global__ void k_count() {
    int row = blockIdx.x * 256 + threadIdx.x;
    const float4* pbp = (const float4*)&g_pB[row * CD];
    float pb[16], u[16];
#pragma unroll
    for (int qq = 0; qq < 4; qq++) {
        float4 v = pbp[qq];
        pb[4 * qq] = v.x; pb[4 * qq + 1] = v.y; pb[4 * qq + 2] = v.z; pb[4 * qq + 3] = v.w;
    }
#pragma unroll
    for (int j = 0; j < 16; j++) u[j] = 0.0f;
    int i = 0;
    float res = __int_as_float(0x7f800000);
    while (res >= 0.01f && i < 200) {
        float s2 = 0.0f;
#pragma unroll
        for (int j = 0; j < 16; j++) {
            float s  = u[j] + pb[j];
            float un = __fsub_rn(u[j], __fmul_rn(0.1f, s));
            un = fminf(fmaxf(un, -1.0f), 1.0f);
            float dd = un - u[j];
            s2 += dd * dd;
            u[j] = un;
        }
        res = __fdiv_rn(sqrtf(s2), 0.1f);
        i++;
    }
    int v = i;
#pragma unroll
    for (int o = 16; o > 0; o >>= 1)
        v = max(v, __shfl_xor_sync(0xffffffffu, v, o));
    if ((threadIdx.x & 31) == 0) atomicMax(&g_K, v);
}

// ---------------- k_final: u = clamp(-(1 - 0.9^(K+6)) * pB) ----------------
__global__ void k_final(float* __restrict__ out) {
    int row = blockIdx.x * 256 + threadIdx.x;
    int n = g_K + 6;
    float f = -(1.0f - powf(0.9f, (float)n));
    const float4* ip = (const float4*)&g_pB[row * CD];
    float4* op = (float4*)&out[row * CD];
#pragma unroll
    for (int qq = 0; qq < 4; qq++) {
        float4 v = ip[qq];
        float4 u;
        u.x = fminf(fmaxf(f * v.x, -1.0f), 1.0f);
        u.y = fminf(fmaxf(f * v.y, -1.0f), 1.0f);
        u.z = fminf(fmaxf(f * v.z, -1.0f), 1.0f);
        u.w = fminf(fmaxf(f * v.w, -1.0f), 1.0f);
        op[qq] = u;
    }
}

// ---------------------------------------------------------------------------
extern "C" void kernel_launch(void* const* d_in, const int* in_sizes, int n_in,
                              void* d_out, int out_size) {
    const float* x  = (const float*)d_in[0];
    const float* t  = (const float*)d_in[1];
    const float* W1 = (const float*)d_in[2];
    const float* b1 = (const float*)d_in[3];
    const float* W2 = (const float*)d_in[4];
    const float* b2 = (const float*)d_in[5];
    const float* W3 = (const float*)d_in[6];
    const float* b3 = (const float*)d_in[7];
    const float* Bm = (const float*)d_in[8];
    float* out = (float*)d_out;

    cudaFuncSetAttribute(k_mlp, cudaFuncAttributeMaxDynamicSharedMemorySize, SM_TOTAL);

    k_prep<<<1, 256>>>(W3, b3, Bm);
    k_quant<<<33, 256>>>(W1, b1, W2, t);
    k_mlp<<<BATCH / 128, 256, SM_TOTAL>>>(x, b2);
    k_count<<<BATCH / 256, 256>>>();
    k_final<<<BATCH / 256, 256>>>(out);
}

// round 9
// speedup vs baseline: 2.0023x; 2.0023x over previous
#include <cuda_runtime.h>
#include <cuda_bf16.h>
#include <cuda_fp16.h>
#include <math.h>
#include <cstdint>

#define BATCH 131072
#define SD 64
#define CD 16
#define HID 256

// ---------------- smem layout (bytes) ----------------
#define SM_A2H   0         // 128 rows x 264 halves (528B stride) = 67584
#define SM_A2L   67584
#define SM_WH    135168    // 256 n-rows x 72 halves (144B stride) = 36864
#define SM_WL    172032    // bf16 lo plane (layer 1 only)
#define SM_W3H   135168    // reuse W buffer: 16 x 264 halves (528B) = 8448
#define SM_W3L   143616
#define SM_B1    208896    // 256 f32
#define SM_B2    209920    // 256 f32
#define SM_B3B   210944    // 16 f32
#define SM_TOTAL 211008

// ---------------- scratch globals ----------------
__device__ float g_W3B[HID * CD];
__device__ float g_b3B[CD];
__device__ float g_pB[BATCH * CD];
__device__ int   g_K;

// ---------------- helpers ----------------
__device__ __forceinline__ uint32_t smem_u32(const void* p) {
    uint32_t a;
    asm("{ .reg .u64 t; cvta.to.shared.u64 t, %1; cvt.u32.u64 %0, t; }" : "=r"(a) : "l"(p));
    return a;
}

// split (a,b) f32 pair into packed bf16x2 hi + lo (residual)
__device__ __forceinline__ void split2(float a, float b, uint32_t& hi, uint32_t& lo) {
    __nv_bfloat16 ha = __float2bfloat16(a), hb = __float2bfloat16(b);
    float ra = a - __bfloat162float(ha);
    float rb = b - __bfloat162float(hb);
    __nv_bfloat16 la = __float2bfloat16(ra), lb = __float2bfloat16(rb);
    hi = ((uint32_t)__bfloat16_as_ushort(hb) << 16) | (uint32_t)__bfloat16_as_ushort(ha);
    lo = ((uint32_t)__bfloat16_as_ushort(lb) << 16) | (uint32_t)__bfloat16_as_ushort(la);
}

// split (a,b) f32 pair into packed fp16x2 hi + lo (residual)
__device__ __forceinline__ void split2h(float a, float b, uint32_t& hi, uint32_t& lo) {
    __half ha = __float2half_rn(a), hb = __float2half_rn(b);
    float ra = a - __half2float(ha);
    float rb = b - __half2float(hb);
    __half la = __float2half_rn(ra), lb = __float2half_rn(rb);
    hi = ((uint32_t)__half_as_ushort(hb) << 16) | (uint32_t)__half_as_ushort(ha);
    lo = ((uint32_t)__half_as_ushort(lb) << 16) | (uint32_t)__half_as_ushort(la);
}

#define LDSM4(v, addr) \
    asm volatile("ldmatrix.sync.aligned.m8n8.x4.shared.b16 {%0,%1,%2,%3}, [%4];" \
        : "=r"((v)[0]), "=r"((v)[1]), "=r"((v)[2]), "=r"((v)[3]) : "r"(addr))

#define MMA(d, a, b0, b1) \
    asm volatile("mma.sync.aligned.m16n8k16.row.col.f32.bf16.bf16.f32 " \
        "{%0,%1,%2,%3}, {%4,%5,%6,%7}, {%8,%9}, {%0,%1,%2,%3};" \
        : "+f"((d)[0]), "+f"((d)[1]), "+f"((d)[2]), "+f"((d)[3]) \
        : "r"((a)[0]), "r"((a)[1]), "r"((a)[2]), "r"((a)[3]), "r"(b0), "r"(b1))

#define MMAH(d, a, b0, b1) \
    asm volatile("mma.sync.aligned.m16n8k16.row.col.f32.f16.f16.f32 " \
        "{%0,%1,%2,%3}, {%4,%5,%6,%7}, {%8,%9}, {%0,%1,%2,%3};" \
        : "+f"((d)[0]), "+f"((d)[1]), "+f"((d)[2]), "+f"((d)[3]) \
        : "r"((a)[0]), "r"((a)[1]), "r"((a)[2]), "r"((a)[3]), "r"(b0), "r"(b1))

// ---------------- k_prep ----------------
__global__ void k_prep(const float* __restrict__ W3, const float* __restrict__ b3,
                       const float* __restrict__ Bm) {
    int h = threadIdx.x;
    float acc[CD];
#pragma unroll
    for (int j = 0; j < CD; j++) acc[j] = 0.0f;
    for (int d = 0; d < SD; d++) {
        float w = W3[h * SD + d];
#pragma unroll
        for (int j = 0; j < CD; j++) acc[j] += w * Bm[d * CD + j];
    }
#pragma unroll
    for (int j = 0; j < CD; j++) g_W3B[h * CD + j] = acc[j];
    if (h < CD) {
        float a = 0.0f;
        for (int d = 0; d < SD; d++) a += b3[d] * Bm[d * CD + h];
        g_b3B[h] = a;
    }
    if (h == 0) g_K = 0;
}

// stage W chunk [64 k x 256 n] f32 -> Wt[n][k] bf16 hi/lo (layer 1)
__device__ __forceinline__ void load_wchunk(char* sm, const float* __restrict__ W,
                                            int krow0, int tid) {
    int n = tid;
#pragma unroll
    for (int it = 0; it < 8; it++) {
        int kb = krow0 + it * 8;
        uint32_t h[4], l[4];
#pragma unroll
        for (int q = 0; q < 4; q++) {
            float w0 = W[(kb + 2 * q) * HID + n];
            float w1 = W[(kb + 2 * q + 1) * HID + n];
            split2(w0, w1, h[q], l[q]);
        }
        *(uint4*)(sm + SM_WH + n * 144 + it * 16) = make_uint4(h[0], h[1], h[2], h[3]);
        *(uint4*)(sm + SM_WL + n * 144 + it * 16) = make_uint4(l[0], l[1], l[2], l[3]);
    }
}

// stage W chunk [64 k x 256 n] f32 -> Wt[n][k] fp16 single plane (layer 2)
__device__ __forceinline__ void load_wchunk_h(char* sm, const float* __restrict__ W,
                                              int krow0, int tid) {
    int n = tid;
#pragma unroll
    for (int it = 0; it < 8; it++) {
        int kb = krow0 + it * 8;
        uint32_t h[4];
#pragma unroll
        for (int q = 0; q < 4; q++) {
            __half w0 = __float2half_rn(W[(kb + 2 * q) * HID + n]);
            __half w1 = __float2half_rn(W[(kb + 2 * q + 1) * HID + n]);
            h[q] = ((uint32_t)__half_as_ushort(w1) << 16) | (uint32_t)__half_as_ushort(w0);
        }
        *(uint4*)(sm + SM_WH + n * 144 + it * 16) = make_uint4(h[0], h[1], h[2], h[3]);
    }
}

// ---------------- fused MLP via mma.sync ----------------
__global__ void __launch_bounds__(256, 1) k_mlp(
    const float* __restrict__ x, const float* __restrict__ t,
    const float* __restrict__ W1, const float* __restrict__ b1,
    const float* __restrict__ W2, const float* __restrict__ b2)
{
    extern __shared__ char sm[];
    uint32_t smb = smem_u32(sm);
    int tid = threadIdx.x, wid = tid >> 5, lid = tid & 31;
    int slab = wid * 16;
    int row0 = blockIdx.x * 128;
    int r0 = lid >> 2, cq = 2 * (lid & 3);

    // coop: biases + W1 chunk
    float t0 = t[0];
    ((float*)(sm + SM_B1))[tid] = fmaf(t0, W1[64 * HID + tid], b1[tid]);
    ((float*)(sm + SM_B2))[tid] = b2[tid];
    if (tid < CD) ((float*)(sm + SM_B3B))[tid] = g_b3B[tid];
    load_wchunk(sm, W1, 0, tid);

    // per-warp: stage own 16 rows of X into own region of A2H, stride 68 f32
    float* Xs = (float*)(sm + SM_A2H + wid * 8448);
#pragma unroll
    for (int i = 0; i < 8; i++) {
        int fid = i * 32 + lid;
        int r = fid >> 4, c4 = fid & 15;
        float4 v = *(const float4*)&x[(row0 + slab + r) * SD + c4 * 4];
        *(float4*)&Xs[r * 68 + c4 * 4] = v;
    }
    __syncwarp();

    // X fragments (bf16 hi/lo) in regs: 4 k-tiles
    uint32_t xh[4][4], xl[4][4];
#pragma unroll
    for (int kt = 0; kt < 4; kt++) {
        int cb = kt * 16 + cq;
        float2 v00 = *(float2*)&Xs[r0 * 68 + cb];
        float2 v10 = *(float2*)&Xs[(r0 + 8) * 68 + cb];
        float2 v01 = *(float2*)&Xs[r0 * 68 + cb + 8];
        float2 v11 = *(float2*)&Xs[(r0 + 8) * 68 + cb + 8];
        split2(v00.x, v00.y, xh[kt][0], xl[kt][0]);
        split2(v10.x, v10.y, xh[kt][1], xl[kt][1]);
        split2(v01.x, v01.y, xh[kt][2], xl[kt][2]);
        split2(v11.x, v11.y, xh[kt][3], xl[kt][3]);
    }
    __syncwarp();
    __syncthreads();

    // ---- Layer 1: D[16x256] = X @ W1 (bf16 3-product) ----
    float d[32][4];
#pragma unroll
    for (int m = 0; m < 32; m++)
#pragma unroll
        for (int q = 0; q < 4; q++) d[m][q] = 0.0f;

#pragma unroll
    for (int kt = 0; kt < 4; kt++) {
#pragma unroll
        for (int n2 = 0; n2 < 16; n2++) {
            uint32_t bh[4], bl[4];
            uint32_t brow = n2 * 16 + ((lid >> 4) << 3) + (lid & 7);
            uint32_t baddr = smb + SM_WH + brow * 144 + (kt * 16 + (lid & 8)) * 2;
            LDSM4(bh, baddr);
            LDSM4(bl, baddr + (SM_WL - SM_WH));
            MMA(d[2 * n2],     xh[kt], bh[0], bh[1]);
            MMA(d[2 * n2],     xh[kt], bl[0], bl[1]);
            MMA(d[2 * n2],     xl[kt], bh[0], bh[1]);
            MMA(d[2 * n2 + 1], xh[kt], bh[2], bh[3]);
            MMA(d[2 * n2 + 1], xh[kt], bl[2], bl[3]);
            MMA(d[2 * n2 + 1], xl[kt], bh[2], bh[3]);
        }
    }

    // ---- relu + bias1 -> A2 (warp-private smem, FP16 hi/lo) ----
    {
        const float* bs1 = (const float*)(sm + SM_B1);
#pragma unroll
        for (int m = 0; m < 32; m++) {
            int c = m * 8 + cq;
            float2 bv = *(const float2*)&bs1[c];
            float h0 = fmaxf(d[m][0] + bv.x, 0.0f);
            float h1 = fmaxf(d[m][1] + bv.y, 0.0f);
            float h2 = fmaxf(d[m][2] + bv.x, 0.0f);
            float h3 = fmaxf(d[m][3] + bv.y, 0.0f);
            uint32_t hi01, lo01, hi23, lo23;
            split2h(h0, h1, hi01, lo01);
            split2h(h2, h3, hi23, lo23);
            int ra = slab + r0;
            *(uint32_t*)(sm + SM_A2H + ra * 528 + c * 2) = hi01;
            *(uint32_t*)(sm + SM_A2L + ra * 528 + c * 2) = lo01;
            *(uint32_t*)(sm + SM_A2H + (ra + 8) * 528 + c * 2) = hi23;
            *(uint32_t*)(sm + SM_A2L + (ra + 8) * 528 + c * 2) = lo23;
        }
    }
    __syncthreads();

    // zero accum for layer 2
#pragma unroll
    for (int m = 0; m < 32; m++)
#pragma unroll
        for (int q = 0; q < 4; q++) d[m][q] = 0.0f;

    // ---- Layer 2: fp16 2-product (A exact hi/lo, W2 single fp16) ----
#pragma unroll 1
    for (int kc = 0; kc < 4; kc++) {
        load_wchunk_h(sm, W2, kc * 64, tid);
        __syncthreads();
#pragma unroll
        for (int kt = 0; kt < 4; kt++) {
            uint32_t ah[4], al[4];
            uint32_t arow = slab + (lid & 15);
            uint32_t acol = kc * 64 + kt * 16 + ((lid >> 4) << 3);
            uint32_t aaddr = smb + SM_A2H + arow * 528 + acol * 2;
            LDSM4(ah, aaddr);
            LDSM4(al, aaddr + (SM_A2L - SM_A2H));
#pragma unroll
            for (int n2 = 0; n2 < 16; n2++) {
                uint32_t bh[4];
                uint32_t brow = n2 * 16 + ((lid >> 4) << 3) + (lid & 7);
                uint32_t baddr = smb + SM_WH + brow * 144 + (kt * 16 + (lid & 8)) * 2;
                LDSM4(bh, baddr);
                MMAH(d[2 * n2],     ah, bh[0], bh[1]);
                MMAH(d[2 * n2],     al, bh[0], bh[1]);
                MMAH(d[2 * n2 + 1], ah, bh[2], bh[3]);
                MMAH(d[2 * n2 + 1], al, bh[2], bh[3]);
            }
        }
        __syncthreads();
    }

    // ---- stage W3B^T [16n x 256k] bf16 hi/lo into W buffer ----
#pragma unroll
    for (int it = 0; it < 8; it++) {
        int pid = tid + it * 256;
        int n = pid & 15, k2 = pid >> 4;
        float v0 = g_W3B[(2 * k2) * CD + n];
        float v1 = g_W3B[(2 * k2 + 1) * CD + n];
        uint32_t hi, lo;
        split2(v0, v1, hi, lo);
        *(uint32_t*)(sm + SM_W3H + n * 528 + k2 * 4) = hi;
        *(uint32_t*)(sm + SM_W3L + n * 528 + k2 * 4) = lo;
    }
    __syncthreads();

    // ---- relu + bias2 -> A3 fragments (bf16 hi/lo) ----
    uint32_t a3h[16][4], a3l[16][4];
    {
        const float* bs2 = (const float*)(sm + SM_B2);
#pragma unroll
        for (int g = 0; g < 16; g++) {
#pragma unroll
            for (int hh = 0; hh < 2; hh++) {
                int m = 2 * g + hh;
                int c = m * 8 + cq;
                float2 bv = *(const float2*)&bs2[c];
                float h0 = fmaxf(d[m][0] + bv.x, 0.0f);
                float h1 = fmaxf(d[m][1] + bv.y, 0.0f);
                float h2 = fmaxf(d[m][2] + bv.x, 0.0f);
                float h3 = fmaxf(d[m][3] + bv.y, 0.0f);
                split2(h0, h1, a3h[g][2 * hh],     a3l[g][2 * hh]);
                split2(h2, h3, a3h[g][2 * hh + 1], a3l[g][2 * hh + 1]);
            }
        }
    }

    // ---- Layer 3: pB[16x16] = H2 @ W3B (bf16 3-product) ----
    float d3a[4] = {0.f, 0.f, 0.f, 0.f};
    float d3b[4] = {0.f, 0.f, 0.f, 0.f};
#pragma unroll
    for (int g = 0; g < 16; g++) {
        uint32_t bh[4], bl[4];
        uint32_t brow = ((lid >> 4) << 3) + (lid & 7);
        uint32_t baddr = smb + SM_W3H + brow * 528 + (g * 16 + (lid & 8)) * 2;
        LDSM4(bh, baddr);
        LDSM4(bl, baddr + (SM_W3L - SM_W3H));
        MMA(d3a, a3h[g], bh[0], bh[1]);
        MMA(d3a, a3h[g], bl[0], bl[1]);
        MMA(d3a, a3l[g], bh[0], bh[1]);
        MMA(d3b, a3h[g], bh[2], bh[3]);
        MMA(d3b, a3h[g], bl[2], bl[3]);
        MMA(d3b, a3l[g], bh[2], bh[3]);
    }

    // ---- epilogue: add b3B, store pB, folded iteration count ----
    float pbA[4], pbB[4];   // rows r, r+8; cols {cq, cq+1, 8+cq, 8+cq+1}
    {
        const float* b3s = (const float*)(sm + SM_B3B);
        float2 bva = *(const float2*)&b3s[cq];
        float2 bvb = *(const float2*)&b3s[8 + cq];
        pbA[0] = d3a[0] + bva.x; pbA[1] = d3a[1] + bva.y;
        pbA[2] = d3b[0] + bvb.x; pbA[3] = d3b[1] + bvb.y;
        pbB[0] = d3a[2] + bva.x; pbB[1] = d3a[3] + bva.y;
        pbB[2] = d3b[2] + bvb.x; pbB[3] = d3b[3] + bvb.y;
        int r = row0 + slab + r0;
        *(float2*)&g_pB[r * CD + cq]           = make_float2(pbA[0], pbA[1]);
        *(float2*)&g_pB[r * CD + 8 + cq]       = make_float2(pbA[2], pbA[3]);
        *(float2*)&g_pB[(r + 8) * CD + cq]     = make_float2(pbB[0], pbB[1]);
        *(float2*)&g_pB[(r + 8) * CD + 8 + cq] = make_float2(pbB[2], pbB[3]);
    }
    {
        float u0[4] = {0.f, 0.f, 0.f, 0.f}, u8[4] = {0.f, 0.f, 0.f, 0.f};
        int k0 = 200, k8 = 200, i = 0;
        bool act0 = true, act8 = true;
        while (__any_sync(0xffffffffu, act0 || act8) && i < 200) {
            float s20 = 0.f, s28 = 0.f;
#pragma unroll
            for (int j = 0; j < 4; j++) {
                float s  = u0[j] + pbA[j];
                float un = __fsub_rn(u0[j], __fmul_rn(0.1f, s));
                un = fminf(fmaxf(un, -1.0f), 1.0f);
                float dd = un - u0[j]; s20 += dd * dd; u0[j] = un;
                s  = u8[j] + pbB[j];
                un = __fsub_rn(u8[j], __fmul_rn(0.1f, s));
                un = fminf(fmaxf(un, -1.0f), 1.0f);
                dd = un - u8[j]; s28 += dd * dd; u8[j] = un;
            }
            s20 += __shfl_xor_sync(0xffffffffu, s20, 1);
            s20 += __shfl_xor_sync(0xffffffffu, s20, 2);
            s28 += __shfl_xor_sync(0xffffffffu, s28, 1);
            s28 += __shfl_xor_sync(0xffffffffu, s28, 2);
            float res0 = __fdiv_rn(sqrtf(s20), 0.1f);
            float res8 = __fdiv_rn(sqrtf(s28), 0.1f);
            i++;
            if (act0 && res0 < 0.01f) { k0 = i; act0 = false; }
            if (act8 && res8 < 0.01f) { k8 = i; act8 = false; }
        }
        int kk = max(k0, k8);
#pragma unroll
        for (int o = 16; o > 0; o >>= 1)
            kk = max(kk, __shfl_xor_sync(0xffffffffu, kk, o));
        if (lid == 0) atomicMax(&g_K, kk);
    }
}

// ---------------- k_final: u = clamp(-(1 - 0.9^(K+6)) * pB) ----------------
__global__ void k_final(float* __restrict__ out) {
    int row = blockIdx.x * 256 + threadIdx.x;
    int n = g_K + 6;
    float f = -(1.0f - powf(0.9f, (float)n));
    const float4* ip = (const float4*)&g_pB[row * CD];
    float4* op = (float4*)&out[row * CD];
#pragma unroll
    for (int q = 0; q < 4; q++) {
        float4 v = ip[q];
        float4 u;
        u.x = fminf(fmaxf(f * v.x, -1.0f), 1.0f);
        u.y = fminf(fmaxf(f * v.y, -1.0f), 1.0f);
        u.z = fminf(fmaxf(f * v.z, -1.0f), 1.0f);
        u.w = fminf(fmaxf(f * v.w, -1.0f), 1.0f);
        op[q] = u;
    }
}

// ---------------------------------------------------------------------------
extern "C" void kernel_launch(void* const* d_in, const int* in_sizes, int n_in,
                              void* d_out, int out_size) {
    const float* x  = (const float*)d_in[0];
    const float* t  = (const float*)d_in[1];
    const float* W1 = (const float*)d_in[2];
    const float* b1 = (const float*)d_in[3];
    const float* W2 = (const float*)d_in[4];
    const float* b2 = (const float*)d_in[5];
    const float* W3 = (const float*)d_in[6];
    const float* b3 = (const float*)d_in[7];
    const float* Bm = (const float*)d_in[8];
    float* out = (float*)d_out;

    cudaFuncSetAttribute(k_mlp, cudaFuncAttributeMaxDynamicSharedMemorySize, SM_TOTAL);

    k_prep<<<1, 256>>>(W3, b3, Bm);
    k_mlp<<<BATCH / 128, 256, SM_TOTAL>>>(x, t, W1, b1, W2, b2);
    k_final<<<BATCH / 256, 256>>>(out);
}